// round 6
// baseline (speedup 1.0000x reference)
#include <cuda_runtime.h>
#include <math.h>
#include <stdint.h>

// Problem constants
#define BSZ 64
#define SEQ 512
#define DIM 768
#define NSPANS 1280
#define LMAX 5
#define H 200
#define G4 800          // 4*H
#define NENT 16
#define MROWS (NSPANS*LMAX)   // 6400

// Scratch (device globals)
__device__ float d_x    [2ll * MROWS * DIM];
__device__ float d_xg   [2ll * MROWS * G4];
__device__ float d_h    [2ll * 2 * NSPANS * H];   // double-buffered: [parity][dir][n][h]
__device__ float d_c    [2ll * NSPANS * H];
__device__ float d_sum  [2ll * NSPANS * H];

#define HBUF (2ll * NSPANS * H)   // one parity buffer

// ---------------------------------------------------------------------------
// Gather
// ---------------------------------------------------------------------------
__global__ void gather_kernel(const float* __restrict__ hidden,
                              const int* __restrict__ tok,
                              const int* __restrict__ slen,
                              const int* __restrict__ sbatch)
{
    int row = blockIdx.x;
    int d4  = threadIdx.x;             // 0..191
    int dir = row / MROWS;
    int r   = row - dir * MROWS;
    int n   = r / LMAX;
    int l   = r - n * LMAX;
    int ln  = slen[n];

    float4 v = make_float4(0.f, 0.f, 0.f, 0.f);
    if (l < ln) {
        int sl = dir ? (ln - 1 - l) : l;
        int t  = tok[n * LMAX + sl];
        int b  = sbatch[n];
        v = *(const float4*)(hidden + ((size_t)b * SEQ + t) * DIM + d4 * 4);
    }
    *(float4*)(d_x + (size_t)row * DIM + d4 * 4) = v;
}

// ---------------------------------------------------------------------------
// tf32 helpers
// ---------------------------------------------------------------------------
__device__ __forceinline__ uint32_t f2tf32(float f) {
    uint32_t r;
    asm("cvt.rna.tf32.f32 %0, %1;" : "=r"(r) : "f"(f));
    return r;
}

__device__ __forceinline__ void mma_tf32(float* c, const uint32_t* a, const uint32_t* b) {
    asm volatile(
        "mma.sync.aligned.m16n8k8.row.col.f32.tf32.tf32.f32 "
        "{%0,%1,%2,%3}, {%4,%5,%6,%7}, {%8,%9}, {%0,%1,%2,%3};"
        : "+f"(c[0]), "+f"(c[1]), "+f"(c[2]), "+f"(c[3])
        : "r"(a[0]), "r"(a[1]), "r"(a[2]), "r"(a[3]), "r"(b[0]), "r"(b[1]));
}

// Fragment-major smem addressing:
// A frag pool: idx = ((k8 * (BM/16) + mtile)*32 + lane)*4 + slot   (uint32)
//   slot = (r>=8 ? 1:0) + (q>=4 ? 2:0), lane = (r&7)*4 + (q&3)
// B frag pool: idx = ((k8 * (BN/8) + ntile)*32 + lane)*2 + slot
//   slot = (q>=4), lane = (rb&7)*4 + (q&3)

// ---------------------------------------------------------------------------
// xg GEMM: xg = x @ W_ih^T + b_ih + b_hh. BM=128,BN=64,BK=32, 8 warps (4Mx2N),
// warp tile 32x32 (MT=2, NT=4).
// ---------------------------------------------------------------------------
__global__ __launch_bounds__(256)
void gemm_xg_kernel(const float* __restrict__ Wf, const float* __restrict__ bif,
                    const float* __restrict__ bhf,
                    const float* __restrict__ Wb, const float* __restrict__ bib,
                    const float* __restrict__ bhb)
{
    const int BM = 128, BN = 64, K = DIM, N = G4;
    __shared__ uint32_t Af[4 * (BM/16) * 32 * 4];   // 16KB
    __shared__ uint32_t Bf[4 * (BN/8)  * 32 * 2];   // 8KB

    int dir = blockIdx.z;
    const float* A  = d_x + (size_t)dir * MROWS * DIM;
    const float* W  = dir ? Wb : Wf;
    const float* c1 = dir ? bib : bif;
    const float* c2 = dir ? bhb : bhf;
    float* C        = d_xg + (size_t)dir * MROWS * G4;

    int tid  = threadIdx.x;
    int warp = tid >> 5, lane = tid & 31;
    int wm = warp & 3, wn = warp >> 2;
    int grp = lane >> 2, qid = lane & 3;
    int m0 = blockIdx.y * BM;
    int n0 = blockIdx.x * BN;

    int lrow = tid >> 3;            // 0..31
    int lcol = (tid & 7) * 4;       // 0..28
    int k8s  = lcol >> 3;           // source k8 within tile
    int half = (lcol >> 2) & 1;

    float acc[2][4][4];
#pragma unroll
    for (int i = 0; i < 2; i++)
#pragma unroll
        for (int j = 0; j < 4; j++)
#pragma unroll
            for (int q = 0; q < 4; q++) acc[i][j][q] = 0.f;

    for (int kt = 0; kt < K; kt += 32) {
        // A tile: 4 float4 per thread
#pragma unroll
        for (int p = 0; p < BM / 32; p++) {
            int m = lrow + p * 32;
            float4 v = *(const float4*)(A + (size_t)(m0 + m) * DIM + kt + lcol);
            int mt = m >> 4, r = m & 15;
            int s = ((r >> 3) & 1) + half * 2;
            uint32_t* dst = Af + (((k8s * (BM/16) + mt) * 32 + (r & 7) * 4) * 4 + s);
            dst[0]  = f2tf32(v.x);
            dst[4]  = f2tf32(v.y);
            dst[8]  = f2tf32(v.z);
            dst[12] = f2tf32(v.w);
        }
        // B tile: 2 float4 per thread
#pragma unroll
        for (int p = 0; p < BN / 32; p++) {
            int n = lrow + p * 32;
            float4 v = make_float4(0.f, 0.f, 0.f, 0.f);
            if (n0 + n < N)
                v = *(const float4*)(W + (size_t)(n0 + n) * DIM + kt + lcol);
            int nt = n >> 3, rb = n & 7;
            uint32_t* dst = Bf + (((k8s * (BN/8) + nt) * 32 + rb * 4) * 2 + half);
            dst[0] = f2tf32(v.x);
            dst[2] = f2tf32(v.y);
            dst[4] = f2tf32(v.z);
            dst[6] = f2tf32(v.w);
        }
        __syncthreads();

#pragma unroll
        for (int ks = 0; ks < 4; ks++) {
            uint4 af[2]; uint2 bf[4];
#pragma unroll
            for (int i = 0; i < 2; i++)
                af[i] = *(const uint4*)(Af + ((ks * (BM/16) + wm * 2 + i) * 32 + lane) * 4);
#pragma unroll
            for (int j = 0; j < 4; j++)
                bf[j] = *(const uint2*)(Bf + ((ks * (BN/8) + wn * 4 + j) * 32 + lane) * 2);
#pragma unroll
            for (int i = 0; i < 2; i++)
#pragma unroll
                for (int j = 0; j < 4; j++)
                    mma_tf32(acc[i][j], (const uint32_t*)&af[i], (const uint32_t*)&bf[j]);
        }
        __syncthreads();
    }

    // Epilogue
#pragma unroll
    for (int i = 0; i < 2; i++) {
#pragma unroll
        for (int j = 0; j < 4; j++) {
            int m = m0 + wm * 32 + i * 16 + grp;
            int n = n0 + wn * 32 + j * 8 + qid * 2;
            if (n < N) {
                float bb0 = c1[n] + c2[n];
                float bb1 = c1[n + 1] + c2[n + 1];
                C[(size_t)m * G4 + n]           = acc[i][j][0] + bb0;
                C[(size_t)m * G4 + n + 1]       = acc[i][j][1] + bb1;
                C[(size_t)(m + 8) * G4 + n]     = acc[i][j][2] + bb0;
                C[(size_t)(m + 8) * G4 + n + 1] = acc[i][j][3] + bb1;
            }
        }
    }
}

// ---------------------------------------------------------------------------
// Fused hh GEMM + LSTM cell. gates = h_in @ W_hh^T + xg[:,t,:], then cell.
// h double-buffered across steps to avoid cross-block read/write races:
// reads d_h[(t-1)&1], writes d_h[t&1].
// BM=128, BN=32 (= 4 gates x 8 hh), BK=32, 8 warps (8Mx1N), warp tile 16x32.
// grid = (25 hh-tiles, 10 m-tiles, 2 dirs)
// ---------------------------------------------------------------------------
__device__ __forceinline__ float sigm(float x) { return 1.f / (1.f + expf(-x)); }

__global__ __launch_bounds__(256)
void gemm_hh_cell_kernel(const float* __restrict__ Wf, const float* __restrict__ Wb,
                         const int* __restrict__ slen, int t)
{
    const int BM = 128, BN = 32, K = H;
    __shared__ uint32_t Af[4 * (BM/16) * 32 * 4];   // 16KB
    __shared__ uint32_t Bf[4 * (BN/8)  * 32 * 2];   // 4KB

    int dir = blockIdx.z;
    const float* A     = d_h + ((t - 1) & 1) * HBUF + (size_t)dir * NSPANS * H;
    float*       h_out = d_h + (t & 1) * HBUF;
    const float* W = dir ? Wb : Wf;

    int tid  = threadIdx.x;
    int warp = tid >> 5, lane = tid & 31;
    int grp = lane >> 2, qid = lane & 3;
    int m0 = blockIdx.y * BM;
    int hh_base = blockIdx.x * 8;

    int lrow = tid >> 3;
    int lcol = (tid & 7) * 4;
    int k8s  = lcol >> 3;
    int half = (lcol >> 2) & 1;

    float acc[4][4];
#pragma unroll
    for (int j = 0; j < 4; j++)
#pragma unroll
        for (int q = 0; q < 4; q++) acc[j][q] = 0.f;

    for (int kt = 0; kt < K; kt += 32) {
        // A tile: rows exact, k guard (K=200)
#pragma unroll
        for (int p = 0; p < BM / 32; p++) {
            int m = lrow + p * 32;
            float4 v = make_float4(0.f, 0.f, 0.f, 0.f);
            int k = kt + lcol;
            if (k < K)
                v = *(const float4*)(A + (size_t)(m0 + m) * H + k);
            int mt = m >> 4, r = m & 15;
            int s = ((r >> 3) & 1) + half * 2;
            uint32_t* dst = Af + (((k8s * (BM/16) + mt) * 32 + (r & 7) * 4) * 4 + s);
            dst[0]  = f2tf32(v.x);
            dst[4]  = f2tf32(v.y);
            dst[8]  = f2tf32(v.z);
            dst[12] = f2tf32(v.w);
        }
        // B tile: 32 rows -> 1 float4 per thread; row map n -> gate*H + hh
        {
            int n = lrow;          // 0..31
            int grow = (n >> 3) * H + hh_base + (n & 7);
            float4 v = make_float4(0.f, 0.f, 0.f, 0.f);
            int k = kt + lcol;
            if (k < K)
                v = *(const float4*)(W + (size_t)grow * H + k);
            int nt = n >> 3, rb = n & 7;
            uint32_t* dst = Bf + (((k8s * (BN/8) + nt) * 32 + rb * 4) * 2 + half);
            dst[0] = f2tf32(v.x);
            dst[2] = f2tf32(v.y);
            dst[4] = f2tf32(v.z);
            dst[6] = f2tf32(v.w);
        }
        __syncthreads();

#pragma unroll
        for (int ks = 0; ks < 4; ks++) {
            uint4 af = *(const uint4*)(Af + ((ks * (BM/16) + warp) * 32 + lane) * 4);
            uint2 bf[4];
#pragma unroll
            for (int j = 0; j < 4; j++)
                bf[j] = *(const uint2*)(Bf + ((ks * (BN/8) + j) * 32 + lane) * 2);
#pragma unroll
            for (int j = 0; j < 4; j++)
                mma_tf32(acc[j], (const uint32_t*)&af, (const uint32_t*)&bf[j]);
        }
        __syncthreads();
    }

    // Fused epilogue: lane holds gates j=0..3 for (m, hc) pairs
    int m_base = m0 + warp * 16 + grp;
#pragma unroll
    for (int c = 0; c < 4; c++) {
        int mrow = m_base + ((c >> 1) * 8);
        int hc   = hh_base + qid * 2 + (c & 1);
        size_t xgb = (size_t)dir * MROWS * G4 + ((size_t)mrow * LMAX + t) * G4 + hc;
        float gi = acc[0][c] + d_xg[xgb];
        float gf = acc[1][c] + d_xg[xgb + H];
        float gg = acc[2][c] + d_xg[xgb + 2 * H];
        float go = acc[3][c] + d_xg[xgb + 3 * H];

        size_t sidx = (size_t)dir * NSPANS * H + (size_t)mrow * H + hc;
        float cn = sigm(gf) * d_c[sidx] + sigm(gi) * tanhf(gg);
        float hn = sigm(go) * tanhf(cn);
        d_c[sidx]   = cn;
        h_out[sidx] = hn;
        float msk = (t < slen[mrow]) ? hn : 0.f;
        d_sum[sidx] += msk;
    }
}

// ---------------------------------------------------------------------------
// t=0 cell: gates = xg[:,0,:] directly (h=0); initializes h (parity 0), c, sum.
// ---------------------------------------------------------------------------
__global__ void lstm_cell0(const int* __restrict__ slen)
{
    int idx = blockIdx.x * blockDim.x + threadIdx.x;
    if (idx >= 2 * NSPANS * H) return;
    int n   = (idx / H) % NSPANS;
    int dir = idx / (H * NSPANS);
    int hh  = idx % H;

    const float* row = d_xg + (size_t)dir * MROWS * G4 + (size_t)n * (LMAX * G4);
    float gi = row[hh];
    float gg = row[2 * H + hh];
    float go = row[3 * H + hh];

    float cn = sigm(gi) * tanhf(gg);     // cprev = 0
    float hn = sigm(go) * tanhf(cn);
    d_c[idx] = cn;
    d_h[idx] = hn;                        // parity-0 buffer
    d_sum[idx] = (0 < slen[n]) ? hn : 0.f;
}

// ---------------------------------------------------------------------------
// Logits
// ---------------------------------------------------------------------------
__global__ void logits_kernel(const float* __restrict__ E,
                              float* __restrict__ out)
{
    int idx = blockIdx.x * blockDim.x + threadIdx.x;
    if (idx >= NSPANS * NENT) return;
    int e = idx % NENT;
    int n = idx / NENT;

    const float4* sf = (const float4*)(d_sum + (size_t)n * H);
    const float4* sb = (const float4*)(d_sum + (size_t)NSPANS * H + (size_t)n * H);
    const float4* er = (const float4*)(E + (size_t)e * 2 * H);

    float acc = 0.f;
#pragma unroll
    for (int j = 0; j < H / 4; j++) {
        float4 a = sf[j], b = er[j];
        acc += a.x * b.x + a.y * b.y + a.z * b.z + a.w * b.w;
    }
#pragma unroll
    for (int j = 0; j < H / 4; j++) {
        float4 a = sb[j], b = er[H / 4 + j];
        acc += a.x * b.x + a.y * b.y + a.z * b.z + a.w * b.w;
    }
    out[idx] = acc;
}

// ---------------------------------------------------------------------------
// Launch — kernel launches only.
// ---------------------------------------------------------------------------
extern "C" void kernel_launch(void* const* d_in, const int* in_sizes, int n_in,
                              void* d_out, int out_size)
{
    const float* hidden = (const float*)d_in[0];
    const int*   tok    = (const int*)d_in[1];
    const int*   slen   = (const int*)d_in[2];
    const int*   sbatch = (const int*)d_in[3];
    const float* W_ih_f = (const float*)d_in[4];
    const float* W_hh_f = (const float*)d_in[5];
    const float* b_ih_f = (const float*)d_in[6];
    const float* b_hh_f = (const float*)d_in[7];
    const float* W_ih_b = (const float*)d_in[8];
    const float* W_hh_b = (const float*)d_in[9];
    const float* b_ih_b = (const float*)d_in[10];
    const float* b_hh_b = (const float*)d_in[11];
    const float* E      = (const float*)d_in[12];
    float* out          = (float*)d_out;

    // 1. Gather + mask + reverse
    gather_kernel<<<2 * MROWS, DIM / 4>>>(hidden, tok, slen, sbatch);

    // 2. xg GEMM (both dirs): grid 13 x 50 x 2
    {
        dim3 grid((G4 + 63) / 64, MROWS / 128, 2);
        gemm_xg_kernel<<<grid, 256>>>(W_ih_f, b_ih_f, b_hh_f,
                                      W_ih_b, b_ih_b, b_hh_b);
    }

    // 3. Recurrence: t=0 pointwise, then 4 fused GEMM+cell steps
    {
        const int ct = 256;
        lstm_cell0<<<(2 * NSPANS * H + ct - 1) / ct, ct>>>(slen);
    }
    for (int t = 1; t < LMAX; t++) {
        dim3 grid(H / 8, NSPANS / 128, 2);   // 25 x 10 x 2
        gemm_hh_cell_kernel<<<grid, 256>>>(W_hh_f, W_hh_b, slen, t);
    }

    // 4. Logits
    logits_kernel<<<(NSPANS * NENT + 127) / 128, 128>>>(E, out);
}

// round 7
// speedup vs baseline: 1.4684x; 1.4684x over previous
#include <cuda_runtime.h>
#include <math.h>
#include <stdint.h>

// Problem constants
#define BSZ 64
#define SEQ 512
#define DIM 768
#define NSPANS 1280
#define LMAX 5
#define H 200
#define G4 800          // 4*H
#define NENT 16
#define MROWS (NSPANS*LMAX)   // 6400

// Scratch (device globals)
__device__ float d_xg   [2ll * MROWS * G4];
__device__ float d_gates[2ll * NSPANS * G4];
__device__ float d_h    [2ll * NSPANS * H];
__device__ float d_c    [2ll * NSPANS * H];
__device__ float d_sum  [2ll * NSPANS * H];

// ---------------------------------------------------------------------------
// tf32 helpers
// ---------------------------------------------------------------------------
__device__ __forceinline__ uint32_t f2tf32(float f) {
    uint32_t r;
    asm("cvt.rna.tf32.f32 %0, %1;" : "=r"(r) : "f"(f));
    return r;
}

__device__ __forceinline__ void mma_tf32(float* c, const uint32_t* a, const uint32_t* b) {
    asm volatile(
        "mma.sync.aligned.m16n8k8.row.col.f32.tf32.tf32.f32 "
        "{%0,%1,%2,%3}, {%4,%5,%6,%7}, {%8,%9}, {%0,%1,%2,%3};"
        : "+f"(c[0]), "+f"(c[1]), "+f"(c[2]), "+f"(c[3])
        : "r"(a[0]), "r"(a[1]), "r"(a[2]), "r"(a[3]), "r"(b[0]), "r"(b[1]));
}

#define BK 32
#define PAD 4
#define LDSROW (BK + PAD)   // 36 uints per row (R4 proven layout)

// ---------------------------------------------------------------------------
// xg GEMM with FUSED GATHER:
// xg = gather(hidden)[dir] @ W_ih^T + b_ih + b_hh
// BM=128, BN=64, 8 warps (4Mx2N), warp tile 32x32 (MT=2, NT=4).
// Row pointers resolved once into smem; masked rows load zeros.
// ---------------------------------------------------------------------------
__global__ __launch_bounds__(256)
void gemm_xg_kernel(const float* __restrict__ hidden,
                    const int* __restrict__ tok,
                    const int* __restrict__ slen,
                    const int* __restrict__ sbatch,
                    const float* __restrict__ Wf, const float* __restrict__ bif,
                    const float* __restrict__ bhf,
                    const float* __restrict__ Wb, const float* __restrict__ bib,
                    const float* __restrict__ bhb)
{
    const int BM = 128, BN = 64, K = DIM, N = G4;
    __shared__ uint32_t As[BM][LDSROW];
    __shared__ uint32_t Bs[BN][LDSROW];
    __shared__ const float* rowptr[BM];

    int dir = blockIdx.z;
    const float* W  = dir ? Wb : Wf;
    const float* c1 = dir ? bib : bif;
    const float* c2 = dir ? bhb : bhf;
    float* C        = d_xg + (size_t)dir * MROWS * G4;

    int tid  = threadIdx.x;
    int warp = tid >> 5, lane = tid & 31;
    int wm = warp & 3, wn = warp >> 2;
    int grp = lane >> 2, qid = lane & 3;
    int m0 = blockIdx.y * BM;
    int n0 = blockIdx.x * BN;

    // Resolve gather row pointers (one per M row of this block)
    if (tid < BM) {
        int r  = m0 + tid;
        int n  = r / LMAX;
        int l  = r - n * LMAX;
        int ln = slen[n];
        const float* p = nullptr;
        if (l < ln) {
            int sl = dir ? (ln - 1 - l) : l;
            int t  = tok[n * LMAX + sl];
            int b  = sbatch[n];
            p = hidden + ((size_t)b * SEQ + t) * DIM;
        }
        rowptr[tid] = p;
    }
    __syncthreads();

    float acc[2][4][4];
#pragma unroll
    for (int i = 0; i < 2; i++)
#pragma unroll
        for (int j = 0; j < 4; j++)
#pragma unroll
            for (int q = 0; q < 4; q++) acc[i][j][q] = 0.f;

    const int lrow = tid >> 3;          // 0..31
    const int lcol = (tid & 7) * 4;     // 0,4,...,28

    for (int kt = 0; kt < K; kt += BK) {
        // A tile: gather-load BM x BK
#pragma unroll
        for (int p = 0; p < BM / 32; p++) {
            int m = lrow + p * 32;
            const float* src = rowptr[m];
            float4 v = make_float4(0.f, 0.f, 0.f, 0.f);
            if (src)
                v = *(const float4*)(src + kt + lcol);
            uint4 t;
            t.x = f2tf32(v.x); t.y = f2tf32(v.y);
            t.z = f2tf32(v.z); t.w = f2tf32(v.w);
            *(uint4*)&As[m][lcol] = t;
        }
        // B tile: BN x BK
#pragma unroll
        for (int p = 0; p < BN / 32; p++) {
            int n = lrow + p * 32;
            float4 v = make_float4(0.f, 0.f, 0.f, 0.f);
            if (n0 + n < N)
                v = *(const float4*)(W + (size_t)(n0 + n) * DIM + kt + lcol);
            uint4 t;
            t.x = f2tf32(v.x); t.y = f2tf32(v.y);
            t.z = f2tf32(v.z); t.w = f2tf32(v.w);
            *(uint4*)&Bs[n][lcol] = t;
        }
        __syncthreads();

#pragma unroll
        for (int ks = 0; ks < BK / 8; ks++) {
            uint32_t af[2][4], bf[4][2];
#pragma unroll
            for (int i = 0; i < 2; i++) {
                int mr = wm * 32 + i * 16;
                af[i][0] = As[mr + grp    ][ks * 8 + qid    ];
                af[i][1] = As[mr + grp + 8][ks * 8 + qid    ];
                af[i][2] = As[mr + grp    ][ks * 8 + qid + 4];
                af[i][3] = As[mr + grp + 8][ks * 8 + qid + 4];
            }
#pragma unroll
            for (int j = 0; j < 4; j++) {
                int nr = wn * 32 + j * 8;
                bf[j][0] = Bs[nr + grp][ks * 8 + qid    ];
                bf[j][1] = Bs[nr + grp][ks * 8 + qid + 4];
            }
#pragma unroll
            for (int i = 0; i < 2; i++)
#pragma unroll
                for (int j = 0; j < 4; j++)
                    mma_tf32(acc[i][j], af[i], bf[j]);
        }
        __syncthreads();
    }

    // Epilogue
#pragma unroll
    for (int i = 0; i < 2; i++) {
#pragma unroll
        for (int j = 0; j < 4; j++) {
            int m = m0 + wm * 32 + i * 16 + grp;
            int n = n0 + wn * 32 + j * 8 + qid * 2;
            if (n < N) {
                float bb0 = c1[n] + c2[n];
                float bb1 = c1[n + 1] + c2[n + 1];
                C[(size_t)m * G4 + n]           = acc[i][j][0] + bb0;
                C[(size_t)m * G4 + n + 1]       = acc[i][j][1] + bb1;
                C[(size_t)(m + 8) * G4 + n]     = acc[i][j][2] + bb0;
                C[(size_t)(m + 8) * G4 + n + 1] = acc[i][j][3] + bb1;
            }
        }
    }
}

// ---------------------------------------------------------------------------
// hh GEMM (R4 proven): gates = h @ W_hh^T + xg[:,t,:]
// BM=64, BN=64, 8 warps (2Mx4N), warp tile 32x16 (MT=2, NT=2).
// ---------------------------------------------------------------------------
__global__ __launch_bounds__(256)
void gemm_hh_kernel(const float* __restrict__ Wf, const float* __restrict__ Wb,
                    int t)
{
    const int BM = 64, BN = 64, K = H, N = G4;
    __shared__ uint32_t As[BM][LDSROW];
    __shared__ uint32_t Bs[BN][LDSROW];

    int dir = blockIdx.z;
    const float* A = d_h + (size_t)dir * NSPANS * H;
    const float* W = dir ? Wb : Wf;
    const float* Cadd = d_xg + (size_t)dir * MROWS * G4 + (size_t)t * G4;
    float* C = d_gates + (size_t)dir * NSPANS * G4;

    int tid  = threadIdx.x;
    int warp = tid >> 5, lane = tid & 31;
    int wm = warp & 1, wn = warp >> 1;
    int grp = lane >> 2, qid = lane & 3;
    int m0 = blockIdx.y * BM;
    int n0 = blockIdx.x * BN;

    float acc[2][2][4];
#pragma unroll
    for (int i = 0; i < 2; i++)
#pragma unroll
        for (int j = 0; j < 2; j++)
#pragma unroll
            for (int q = 0; q < 4; q++) acc[i][j][q] = 0.f;

    const int lrow = tid >> 3;          // 0..31
    const int lcol = (tid & 7) * 4;

    for (int kt = 0; kt < K; kt += BK) {
        // A tile
#pragma unroll
        for (int p = 0; p < BM / 32; p++) {
            int m = lrow + p * 32;
            int k = kt + lcol;
            float4 v = make_float4(0.f, 0.f, 0.f, 0.f);
            if (k < K)
                v = *(const float4*)(A + (size_t)(m0 + m) * H + k);
            uint4 tt;
            tt.x = f2tf32(v.x); tt.y = f2tf32(v.y);
            tt.z = f2tf32(v.z); tt.w = f2tf32(v.w);
            *(uint4*)&As[m][lcol] = tt;
        }
        // B tile
#pragma unroll
        for (int p = 0; p < BN / 32; p++) {
            int n = lrow + p * 32;
            int k = kt + lcol;
            float4 v = make_float4(0.f, 0.f, 0.f, 0.f);
            if ((n0 + n) < N && k < K)
                v = *(const float4*)(W + (size_t)(n0 + n) * H + k);
            uint4 tt;
            tt.x = f2tf32(v.x); tt.y = f2tf32(v.y);
            tt.z = f2tf32(v.z); tt.w = f2tf32(v.w);
            *(uint4*)&Bs[n][lcol] = tt;
        }
        __syncthreads();

#pragma unroll
        for (int ks = 0; ks < BK / 8; ks++) {
            uint32_t af[2][4], bf[2][2];
#pragma unroll
            for (int i = 0; i < 2; i++) {
                int mr = wm * 32 + i * 16;
                af[i][0] = As[mr + grp    ][ks * 8 + qid    ];
                af[i][1] = As[mr + grp + 8][ks * 8 + qid    ];
                af[i][2] = As[mr + grp    ][ks * 8 + qid + 4];
                af[i][3] = As[mr + grp + 8][ks * 8 + qid + 4];
            }
#pragma unroll
            for (int j = 0; j < 2; j++) {
                int nr = wn * 16 + j * 8;
                bf[j][0] = Bs[nr + grp][ks * 8 + qid    ];
                bf[j][1] = Bs[nr + grp][ks * 8 + qid + 4];
            }
#pragma unroll
            for (int i = 0; i < 2; i++)
#pragma unroll
                for (int j = 0; j < 2; j++)
                    mma_tf32(acc[i][j], af[i], bf[j]);
        }
        __syncthreads();
    }

    // Epilogue: += xg slice
#pragma unroll
    for (int i = 0; i < 2; i++) {
#pragma unroll
        for (int j = 0; j < 2; j++) {
            int m = m0 + wm * 32 + i * 16 + grp;
            int n = n0 + wn * 16 + j * 8 + qid * 2;
            if (n < N) {
                C[(size_t)m * G4 + n] =
                    acc[i][j][0] + Cadd[(size_t)m * (LMAX * G4) + n];
                C[(size_t)m * G4 + n + 1] =
                    acc[i][j][1] + Cadd[(size_t)m * (LMAX * G4) + n + 1];
                C[(size_t)(m + 8) * G4 + n] =
                    acc[i][j][2] + Cadd[(size_t)(m + 8) * (LMAX * G4) + n];
                C[(size_t)(m + 8) * G4 + n + 1] =
                    acc[i][j][3] + Cadd[(size_t)(m + 8) * (LMAX * G4) + n + 1];
            }
        }
    }
}

// ---------------------------------------------------------------------------
// LSTM cell pointwise update
// ---------------------------------------------------------------------------
__device__ __forceinline__ float sigm(float x) { return 1.f / (1.f + expf(-x)); }

__global__ void lstm_cell(const int* __restrict__ slen, int t)
{
    int idx = blockIdx.x * blockDim.x + threadIdx.x;
    if (idx >= 2 * NSPANS * H) return;
    int hh  = idx % H;
    int n   = (idx / H) % NSPANS;
    int dir = idx / (H * NSPANS);

    const float* row;
    if (t == 0)
        row = d_xg + (size_t)dir * MROWS * G4 + (size_t)n * (LMAX * G4);
    else
        row = d_gates + (size_t)dir * NSPANS * G4 + (size_t)n * G4;

    float gi = row[hh];
    float gf = row[H + hh];
    float gg = row[2 * H + hh];
    float go = row[3 * H + hh];

    float cprev = (t == 0) ? 0.f : d_c[idx];
    float cn = sigm(gf) * cprev + sigm(gi) * tanhf(gg);
    float hn = sigm(go) * tanhf(cn);
    d_c[idx] = cn;
    d_h[idx] = hn;

    float m = (t < slen[n]) ? hn : 0.f;
    d_sum[idx] = (t == 0) ? m : (d_sum[idx] + m);
}

// ---------------------------------------------------------------------------
// Logits
// ---------------------------------------------------------------------------
__global__ void logits_kernel(const float* __restrict__ E,
                              float* __restrict__ out)
{
    int idx = blockIdx.x * blockDim.x + threadIdx.x;
    if (idx >= NSPANS * NENT) return;
    int e = idx % NENT;
    int n = idx / NENT;

    const float4* sf = (const float4*)(d_sum + (size_t)n * H);
    const float4* sb = (const float4*)(d_sum + (size_t)NSPANS * H + (size_t)n * H);
    const float4* er = (const float4*)(E + (size_t)e * 2 * H);

    float acc = 0.f;
#pragma unroll
    for (int j = 0; j < H / 4; j++) {
        float4 a = sf[j], b = er[j];
        acc += a.x * b.x + a.y * b.y + a.z * b.z + a.w * b.w;
    }
#pragma unroll
    for (int j = 0; j < H / 4; j++) {
        float4 a = sb[j], b = er[H / 4 + j];
        acc += a.x * b.x + a.y * b.y + a.z * b.z + a.w * b.w;
    }
    out[idx] = acc;
}

// ---------------------------------------------------------------------------
// Launch — kernel launches only.
// ---------------------------------------------------------------------------
extern "C" void kernel_launch(void* const* d_in, const int* in_sizes, int n_in,
                              void* d_out, int out_size)
{
    const float* hidden = (const float*)d_in[0];
    const int*   tok    = (const int*)d_in[1];
    const int*   slen   = (const int*)d_in[2];
    const int*   sbatch = (const int*)d_in[3];
    const float* W_ih_f = (const float*)d_in[4];
    const float* W_hh_f = (const float*)d_in[5];
    const float* b_ih_f = (const float*)d_in[6];
    const float* b_hh_f = (const float*)d_in[7];
    const float* W_ih_b = (const float*)d_in[8];
    const float* W_hh_b = (const float*)d_in[9];
    const float* b_ih_b = (const float*)d_in[10];
    const float* b_hh_b = (const float*)d_in[11];
    const float* E      = (const float*)d_in[12];
    float* out          = (float*)d_out;

    // 1. xg GEMM with fused gather (both dirs): grid 13 x 50 x 2
    {
        dim3 grid((G4 + 63) / 64, MROWS / 128, 2);
        gemm_xg_kernel<<<grid, 256>>>(hidden, tok, slen, sbatch,
                                      W_ih_f, b_ih_f, b_hh_f,
                                      W_ih_b, b_ih_b, b_hh_b);
    }

    // 2. Recurrence
    const int ct = 256;
    const int cb = (2 * NSPANS * H + ct - 1) / ct;
    lstm_cell<<<cb, ct>>>(slen, 0);

    for (int t = 1; t < LMAX; t++) {
        dim3 grid((G4 + 63) / 64, NSPANS / 64, 2);   // 13 x 20 x 2
        gemm_hh_kernel<<<grid, 256>>>(W_hh_f, W_hh_b, t);
        lstm_cell<<<cb, ct>>>(slen, t);
    }

    // 3. Logits
    logits_kernel<<<(NSPANS * NENT + 127) / 128, 128>>>(E, out);
}

// round 8
// speedup vs baseline: 1.9351x; 1.3179x over previous
#include <cuda_runtime.h>
#include <math.h>
#include <stdint.h>

// Problem constants
#define BSZ 64
#define SEQ 512
#define DIM 768
#define NSPANS 1280
#define LMAX 5
#define H 200
#define G4 800          // 4*H
#define NENT 16
#define MROWS (NSPANS*LMAX)   // 6400

// Scratch (device globals)
__device__ float d_xg    [2ll * MROWS * G4];       // compacted rows per dir
__device__ float d_h     [2ll * 2 * NSPANS * H];   // double-buffered [parity]
__device__ float d_c     [2ll * NSPANS * H];
__device__ float d_sum   [2ll * NSPANS * H];
__device__ int   d_offset[NSPANS + 1];             // exclusive prefix of slen
__device__ int   d_rowmap[MROWS];                  // compacted row -> (n<<3)|l

#define HBUF (2ll * NSPANS * H)

// ---------------------------------------------------------------------------
// tf32 helpers
// ---------------------------------------------------------------------------
__device__ __forceinline__ uint32_t f2tf32(float f) {
    uint32_t r;
    asm("cvt.rna.tf32.f32 %0, %1;" : "=r"(r) : "f"(f));
    return r;
}

__device__ __forceinline__ void mma_tf32(float* c, const uint32_t* a, const uint32_t* b) {
    asm volatile(
        "mma.sync.aligned.m16n8k8.row.col.f32.tf32.tf32.f32 "
        "{%0,%1,%2,%3}, {%4,%5,%6,%7}, {%8,%9}, {%0,%1,%2,%3};"
        : "+f"(c[0]), "+f"(c[1]), "+f"(c[2]), "+f"(c[3])
        : "r"(a[0]), "r"(a[1]), "r"(a[2]), "r"(a[3]), "r"(b[0]), "r"(b[1]));
}

#define BK 32
#define PAD 4
#define LDSROW (BK + PAD)   // 36 uints per row (R4 proven layout)

// ---------------------------------------------------------------------------
// Compaction: offsets = exclusive-prefix(slen); rowmap[off+l] = (n<<3)|l
// 256 threads, 5 spans each.
// ---------------------------------------------------------------------------
__global__ void compact_kernel(const int* __restrict__ slen)
{
    __shared__ int part[256];
    int tid = threadIdx.x;
    int base = tid * 5;
    int loc[5], s = 0;
#pragma unroll
    for (int i = 0; i < 5; i++) { loc[i] = s; s += slen[base + i]; }
    part[tid] = s;
    __syncthreads();
    // inclusive scan
    for (int off = 1; off < 256; off <<= 1) {
        int v = (tid >= off) ? part[tid - off] : 0;
        __syncthreads();
        part[tid] += v;
        __syncthreads();
    }
    int pre = (tid == 0) ? 0 : part[tid - 1];
#pragma unroll
    for (int i = 0; i < 5; i++) {
        int n = base + i;
        int off = pre + loc[i];
        d_offset[n] = off;
        int ln = slen[n];
        for (int l = 0; l < ln; l++)
            d_rowmap[off + l] = (n << 3) | l;
    }
    if (tid == 255) d_offset[NSPANS] = part[255];
}

// ---------------------------------------------------------------------------
// xg GEMM, fused gather, COMPACTED rows:
// xg[r] = hidden[span(r), tok] @ W_ih^T + b_ih + b_hh, r < count
// BM=128, BN=64, 8 warps (4Mx2N), warp tile 32x32.
// ---------------------------------------------------------------------------
__global__ __launch_bounds__(256)
void gemm_xg_kernel(const float* __restrict__ hidden,
                    const int* __restrict__ tok,
                    const int* __restrict__ slen,
                    const int* __restrict__ sbatch,
                    const float* __restrict__ Wf, const float* __restrict__ bif,
                    const float* __restrict__ bhf,
                    const float* __restrict__ Wb, const float* __restrict__ bib,
                    const float* __restrict__ bhb)
{
    const int BM = 128, BN = 64, K = DIM, N = G4;
    int m0 = blockIdx.y * BM;
    int count = d_offset[NSPANS];
    if (m0 >= count) return;

    __shared__ uint32_t As[BM][LDSROW];
    __shared__ uint32_t Bs[BN][LDSROW];
    __shared__ const float* rowptr[BM];

    int dir = blockIdx.z;
    const float* W  = dir ? Wb : Wf;
    const float* c1 = dir ? bib : bif;
    const float* c2 = dir ? bhb : bhf;
    float* C        = d_xg + (size_t)dir * MROWS * G4;

    int tid  = threadIdx.x;
    int warp = tid >> 5, lane = tid & 31;
    int wm = warp & 3, wn = warp >> 2;
    int grp = lane >> 2, qid = lane & 3;
    int n0 = blockIdx.x * BN;

    if (tid < BM) {
        int r = m0 + tid;
        const float* p = nullptr;
        if (r < count) {
            int rm = d_rowmap[r];
            int n  = rm >> 3;
            int l  = rm & 7;
            int ln = slen[n];
            int sl = dir ? (ln - 1 - l) : l;
            int t  = tok[n * LMAX + sl];
            int b  = sbatch[n];
            p = hidden + ((size_t)b * SEQ + t) * DIM;
        }
        rowptr[tid] = p;
    }
    __syncthreads();

    float acc[2][4][4];
#pragma unroll
    for (int i = 0; i < 2; i++)
#pragma unroll
        for (int j = 0; j < 4; j++)
#pragma unroll
            for (int q = 0; q < 4; q++) acc[i][j][q] = 0.f;

    const int lrow = tid >> 3;
    const int lcol = (tid & 7) * 4;

    for (int kt = 0; kt < K; kt += BK) {
#pragma unroll
        for (int p = 0; p < BM / 32; p++) {
            int m = lrow + p * 32;
            const float* src = rowptr[m];
            float4 v = make_float4(0.f, 0.f, 0.f, 0.f);
            if (src)
                v = *(const float4*)(src + kt + lcol);
            uint4 t;
            t.x = f2tf32(v.x); t.y = f2tf32(v.y);
            t.z = f2tf32(v.z); t.w = f2tf32(v.w);
            *(uint4*)&As[m][lcol] = t;
        }
#pragma unroll
        for (int p = 0; p < BN / 32; p++) {
            int n = lrow + p * 32;
            float4 v = make_float4(0.f, 0.f, 0.f, 0.f);
            if (n0 + n < N)
                v = *(const float4*)(W + (size_t)(n0 + n) * DIM + kt + lcol);
            uint4 t;
            t.x = f2tf32(v.x); t.y = f2tf32(v.y);
            t.z = f2tf32(v.z); t.w = f2tf32(v.w);
            *(uint4*)&Bs[n][lcol] = t;
        }
        __syncthreads();

#pragma unroll
        for (int ks = 0; ks < BK / 8; ks++) {
            uint32_t af[2][4], bf[4][2];
#pragma unroll
            for (int i = 0; i < 2; i++) {
                int mr = wm * 32 + i * 16;
                af[i][0] = As[mr + grp    ][ks * 8 + qid    ];
                af[i][1] = As[mr + grp + 8][ks * 8 + qid    ];
                af[i][2] = As[mr + grp    ][ks * 8 + qid + 4];
                af[i][3] = As[mr + grp + 8][ks * 8 + qid + 4];
            }
#pragma unroll
            for (int j = 0; j < 4; j++) {
                int nr = wn * 32 + j * 8;
                bf[j][0] = Bs[nr + grp][ks * 8 + qid    ];
                bf[j][1] = Bs[nr + grp][ks * 8 + qid + 4];
            }
#pragma unroll
            for (int i = 0; i < 2; i++)
#pragma unroll
                for (int j = 0; j < 4; j++)
                    mma_tf32(acc[i][j], af[i], bf[j]);
        }
        __syncthreads();
    }

#pragma unroll
    for (int i = 0; i < 2; i++) {
#pragma unroll
        for (int j = 0; j < 4; j++) {
            int m = m0 + wm * 32 + i * 16 + grp;
            int n = n0 + wn * 32 + j * 8 + qid * 2;
            if (n < N) {
                float bb0 = c1[n] + c2[n];
                float bb1 = c1[n + 1] + c2[n + 1];
                C[(size_t)m * G4 + n]           = acc[i][j][0] + bb0;
                C[(size_t)m * G4 + n + 1]       = acc[i][j][1] + bb1;
                C[(size_t)(m + 8) * G4 + n]     = acc[i][j][2] + bb0;
                C[(size_t)(m + 8) * G4 + n + 1] = acc[i][j][3] + bb1;
            }
        }
    }
}

// ---------------------------------------------------------------------------
// Fused hh GEMM + cell. BM=64 spans, BN=64 = 4 gates x 16 hh.
// Column map: local n -> W row (n>>4)*H + hh_base + (n&15).
// h double-buffered: reads parity (t-1)&1, writes t&1.
// grid = (13, 20, 2)
// ---------------------------------------------------------------------------
__device__ __forceinline__ float sigm(float x) { return 1.f / (1.f + expf(-x)); }

__global__ __launch_bounds__(256)
void gemm_hh_cell_kernel(const float* __restrict__ Wf, const float* __restrict__ Wb,
                         const int* __restrict__ slen, int t)
{
    const int BM = 64, BN = 64, K = H;
    __shared__ uint32_t As[BM][LDSROW];
    __shared__ uint32_t Bs[BN][LDSROW];
    __shared__ float Gs[BM][BN + 4];
    __shared__ int   xrow[BM];
    __shared__ int   lens[BM];

    int dir = blockIdx.z;
    const float* A     = d_h + ((t - 1) & 1) * HBUF + (size_t)dir * NSPANS * H;
    float*       h_out = d_h + (t & 1) * HBUF;
    const float* W  = dir ? Wb : Wf;
    const float* XG = d_xg + (size_t)dir * MROWS * G4;

    int tid  = threadIdx.x;
    int warp = tid >> 5, lane = tid & 31;
    int wm = warp & 1, wn = warp >> 1;
    int grp = lane >> 2, qid = lane & 3;
    int m0 = blockIdx.y * BM;
    int hh_base = blockIdx.x * 16;

    if (tid < BM) {
        int n  = m0 + tid;
        int ln = slen[n];
        lens[tid] = ln;
        int tt = t < ln ? t : (ln - 1);
        xrow[tid] = d_offset[n] + tt;
    }

    float acc[2][2][4];
#pragma unroll
    for (int i = 0; i < 2; i++)
#pragma unroll
        for (int j = 0; j < 2; j++)
#pragma unroll
            for (int q = 0; q < 4; q++) acc[i][j][q] = 0.f;

    const int lrow = tid >> 3;
    const int lcol = (tid & 7) * 4;

    for (int kt = 0; kt < K; kt += BK) {
#pragma unroll
        for (int p = 0; p < BM / 32; p++) {
            int m = lrow + p * 32;
            int k = kt + lcol;
            float4 v = make_float4(0.f, 0.f, 0.f, 0.f);
            if (k < K)
                v = *(const float4*)(A + (size_t)(m0 + m) * H + k);
            uint4 tt;
            tt.x = f2tf32(v.x); tt.y = f2tf32(v.y);
            tt.z = f2tf32(v.z); tt.w = f2tf32(v.w);
            *(uint4*)&As[m][lcol] = tt;
        }
#pragma unroll
        for (int p = 0; p < BN / 32; p++) {
            int n = lrow + p * 32;
            int hhi = hh_base + (n & 15);
            int grow = (n >> 4) * H + hhi;
            int k = kt + lcol;
            float4 v = make_float4(0.f, 0.f, 0.f, 0.f);
            if (hhi < H && k < K)
                v = *(const float4*)(W + (size_t)grow * H + k);
            uint4 tt;
            tt.x = f2tf32(v.x); tt.y = f2tf32(v.y);
            tt.z = f2tf32(v.z); tt.w = f2tf32(v.w);
            *(uint4*)&Bs[n][lcol] = tt;
        }
        __syncthreads();

#pragma unroll
        for (int ks = 0; ks < BK / 8; ks++) {
            uint32_t af[2][4], bf[2][2];
#pragma unroll
            for (int i = 0; i < 2; i++) {
                int mr = wm * 32 + i * 16;
                af[i][0] = As[mr + grp    ][ks * 8 + qid    ];
                af[i][1] = As[mr + grp + 8][ks * 8 + qid    ];
                af[i][2] = As[mr + grp    ][ks * 8 + qid + 4];
                af[i][3] = As[mr + grp + 8][ks * 8 + qid + 4];
            }
#pragma unroll
            for (int j = 0; j < 2; j++) {
                int nr = wn * 16 + j * 8;
                bf[j][0] = Bs[nr + grp][ks * 8 + qid    ];
                bf[j][1] = Bs[nr + grp][ks * 8 + qid + 4];
            }
#pragma unroll
            for (int i = 0; i < 2; i++)
#pragma unroll
                for (int j = 0; j < 2; j++)
                    mma_tf32(acc[i][j], af[i], bf[j]);
        }
        __syncthreads();
    }

    // Stage gate tile to smem
#pragma unroll
    for (int i = 0; i < 2; i++) {
#pragma unroll
        for (int j = 0; j < 2; j++) {
            int m = wm * 32 + i * 16 + grp;
            int n = wn * 16 + j * 8 + qid * 2;
            Gs[m][n]         = acc[i][j][0];
            Gs[m][n + 1]     = acc[i][j][1];
            Gs[m + 8][n]     = acc[i][j][2];
            Gs[m + 8][n + 1] = acc[i][j][3];
        }
    }
    __syncthreads();

    // Cell phase: 64x16 items, 4 per thread
#pragma unroll
    for (int it = 0; it < 4; it++) {
        int id = tid + it * 256;
        int m  = id >> 4;
        int hl = id & 15;
        int hhi = hh_base + hl;
        if (hhi >= H) continue;

        size_t xb = (size_t)xrow[m] * G4 + hhi;
        float gi = Gs[m][hl     ] + XG[xb];
        float gf = Gs[m][16 + hl] + XG[xb + H];
        float gg = Gs[m][32 + hl] + XG[xb + 2 * H];
        float go = Gs[m][48 + hl] + XG[xb + 3 * H];

        size_t sidx = (size_t)dir * NSPANS * H + (size_t)(m0 + m) * H + hhi;
        float cn = sigm(gf) * d_c[sidx] + sigm(gi) * tanhf(gg);
        float hn = sigm(go) * tanhf(cn);
        d_c[sidx] = cn;
        h_out[(size_t)dir * NSPANS * H + (size_t)(m0 + m) * H + hhi] = hn;
        if (t < lens[m]) d_sum[sidx] += hn;
    }
}

// ---------------------------------------------------------------------------
// t=0 cell: gates = xg[offset[n]] (h=0). Writes h parity 0, c, sum.
// ---------------------------------------------------------------------------
__global__ void lstm_cell0(const int* __restrict__ slen)
{
    int idx = blockIdx.x * blockDim.x + threadIdx.x;
    if (idx >= 2 * NSPANS * H) return;
    int hh  = idx % H;
    int n   = (idx / H) % NSPANS;
    int dir = idx / (H * NSPANS);

    int row = d_offset[n];                     // t=0 always valid (slen >= 1)
    const float* g = d_xg + (size_t)dir * MROWS * G4 + (size_t)row * G4;
    float gi = g[hh];
    float gg = g[2 * H + hh];
    float go = g[3 * H + hh];

    float cn = sigm(gi) * tanhf(gg);
    float hn = sigm(go) * tanhf(cn);
    d_c[idx] = cn;
    d_h[idx] = hn;                              // parity 0
    d_sum[idx] = hn;                            // slen >= 1 -> t=0 in mask
}

// ---------------------------------------------------------------------------
// Logits
// ---------------------------------------------------------------------------
__global__ void logits_kernel(const float* __restrict__ E,
                              float* __restrict__ out)
{
    int idx = blockIdx.x * blockDim.x + threadIdx.x;
    if (idx >= NSPANS * NENT) return;
    int e = idx % NENT;
    int n = idx / NENT;

    const float4* sf = (const float4*)(d_sum + (size_t)n * H);
    const float4* sb = (const float4*)(d_sum + (size_t)NSPANS * H + (size_t)n * H);
    const float4* er = (const float4*)(E + (size_t)e * 2 * H);

    float acc = 0.f;
#pragma unroll
    for (int j = 0; j < H / 4; j++) {
        float4 a = sf[j], b = er[j];
        acc += a.x * b.x + a.y * b.y + a.z * b.z + a.w * b.w;
    }
#pragma unroll
    for (int j = 0; j < H / 4; j++) {
        float4 a = sb[j], b = er[H / 4 + j];
        acc += a.x * b.x + a.y * b.y + a.z * b.z + a.w * b.w;
    }
    out[idx] = acc;
}

// ---------------------------------------------------------------------------
// Launch
// ---------------------------------------------------------------------------
extern "C" void kernel_launch(void* const* d_in, const int* in_sizes, int n_in,
                              void* d_out, int out_size)
{
    const float* hidden = (const float*)d_in[0];
    const int*   tok    = (const int*)d_in[1];
    const int*   slen   = (const int*)d_in[2];
    const int*   sbatch = (const int*)d_in[3];
    const float* W_ih_f = (const float*)d_in[4];
    const float* W_hh_f = (const float*)d_in[5];
    const float* b_ih_f = (const float*)d_in[6];
    const float* b_hh_f = (const float*)d_in[7];
    const float* W_ih_b = (const float*)d_in[8];
    const float* W_hh_b = (const float*)d_in[9];
    const float* b_ih_b = (const float*)d_in[10];
    const float* b_hh_b = (const float*)d_in[11];
    const float* E      = (const float*)d_in[12];
    float* out          = (float*)d_out;

    // 0. Row compaction
    compact_kernel<<<1, 256>>>(slen);

    // 1. xg GEMM, fused gather, compacted rows: grid 13 x 50 x 2 (blocks self-trim)
    {
        dim3 grid((G4 + 63) / 64, MROWS / 128, 2);
        gemm_xg_kernel<<<grid, 256>>>(hidden, tok, slen, sbatch,
                                      W_ih_f, b_ih_f, b_hh_f,
                                      W_ih_b, b_ih_b, b_hh_b);
    }

    // 2. Recurrence
    {
        const int ct = 256;
        lstm_cell0<<<(2 * NSPANS * H + ct - 1) / ct, ct>>>(slen);
    }
    for (int t = 1; t < LMAX; t++) {
        dim3 grid((H + 15) / 16, NSPANS / 64, 2);   // 13 x 20 x 2
        gemm_hh_cell_kernel<<<grid, 256>>>(W_hh_f, W_hh_b, slen, t);
    }

    // 3. Logits
    logits_kernel<<<(NSPANS * NENT + 127) / 128, 128>>>(E, out);
}